// round 15
// baseline (speedup 1.0000x reference)
#include <cuda_runtime.h>
#include <cuda_fp16.h>
#include <cstdint>
#include <math.h>

#define BB 4
#define NN 2048
#define CC 64
#define HH 8
#define SCALE 0.125f
#define LOG2E 1.44269504088896340736f

// Scratch (allocation-free)
__device__ __half g_ph[HH*CC*CC],  g_pl[HH*CC*CC];         // Wproj split hi/lo
__device__ __half g_Qh[BB*HH*NN*CC];
__device__ __half g_Kh[BB*HH*NN*CC];
__device__ __half g_Vh[BB*HH*NN*CC];

__device__ __forceinline__ uint32_t smem_u32(const void* p) {
    uint32_t a;
    asm("{ .reg .u64 t; cvta.to.shared.u64 t, %1; cvt.u32.u64 %0, t; }" : "=r"(a) : "l"(p));
    return a;
}
__device__ __forceinline__ void cp16(uint32_t dst, const void* src) {
    asm volatile("cp.async.cg.shared.global [%0], [%1], 16;" :: "r"(dst), "l"(src));
}
#define CP_COMMIT() asm volatile("cp.async.commit_group;" ::: "memory")
#define CP_WAIT(n)  asm volatile("cp.async.wait_group %0;" :: "n"(n) : "memory")

__device__ __forceinline__ void redg2(float* addr, float a, float b) {
    asm volatile("red.global.add.v2.f32 [%0], {%1, %2};" :: "l"(addr), "f"(a), "f"(b) : "memory");
}

__device__ __forceinline__ void mma_f16(float* c, uint32_t a0, uint32_t a1,
                                        uint32_t a2, uint32_t a3,
                                        uint32_t b0, uint32_t b1) {
    asm volatile(
        "mma.sync.aligned.m16n8k16.row.col.f32.f16.f16.f32 "
        "{%0,%1,%2,%3}, {%4,%5,%6,%7}, {%8,%9}, {%0,%1,%2,%3};"
        : "+f"(c[0]), "+f"(c[1]), "+f"(c[2]), "+f"(c[3])
        : "r"(a0), "r"(a1), "r"(a2), "r"(a3), "r"(b0), "r"(b1));
}
__device__ __forceinline__ void mma_f16h(uint32_t* c, uint32_t a0, uint32_t a1,
                                         uint32_t a2, uint32_t a3,
                                         uint32_t b0, uint32_t b1) {
    asm volatile(
        "mma.sync.aligned.m16n8k16.row.col.f16.f16.f16.f16 "
        "{%0,%1}, {%2,%3,%4,%5}, {%6,%7}, {%0,%1};"
        : "+r"(c[0]), "+r"(c[1])
        : "r"(a0), "r"(a1), "r"(a2), "r"(a3), "r"(b0), "r"(b1));
}
__device__ __forceinline__ void ldsm4(uint32_t* r, uint32_t addr) {
    asm volatile("ldmatrix.sync.aligned.m8n8.x4.shared.b16 {%0,%1,%2,%3}, [%4];"
                 : "=r"(r[0]), "=r"(r[1]), "=r"(r[2]), "=r"(r[3]) : "r"(addr));
}
__device__ __forceinline__ void ldsm4t(uint32_t* r, uint32_t addr) {
    asm volatile("ldmatrix.sync.aligned.m8n8.x4.trans.shared.b16 {%0,%1,%2,%3}, [%4];"
                 : "=r"(r[0]), "=r"(r[1]), "=r"(r[2]), "=r"(r[3]) : "r"(addr));
}
__device__ __forceinline__ uint32_t ex2h2(uint32_t p) {
    uint32_t r; asm("ex2.approx.f16x2 %0, %1;" : "=r"(r) : "r"(p)); return r;
}
__device__ __forceinline__ uint32_t hadd2u(uint32_t a, uint32_t b) {
    __half2 r = __hadd2(*(__half2*)&a, *(__half2*)&b);
    return *(uint32_t*)&r;
}
__device__ __forceinline__ uint32_t packh2(float a, float b) {
    __half2 h = __floats2half2_rn(a, b);
    return *(uint32_t*)&h;
}
__device__ __forceinline__ void split16(float v, __half& hi, __half& lo) {
    hi = __float2half_rn(v);
    lo = __float2half_rn(v - __half2float(hi));
}

#define PAD  72
#define PAD2 136

// ---------------------------------------------------------------------------
// Pre-pass (small): blocks [0,32) split Wproj; [32,544) prefill out with bias
// ---------------------------------------------------------------------------
__global__ void __launch_bounds__(256) prepass(const float* __restrict__ Wp,
                                               const float* __restrict__ bias,
                                               float* __restrict__ out) {
    const int blk = blockIdx.x;
    if (blk < 32) {
        int i = (blk * 256 + threadIdx.x) * 4;
        float4 v = *(const float4*)(Wp + i);
        __half h0,l0,h1,l1,h2,l2,h3,l3;
        split16(v.x,h0,l0); split16(v.y,h1,l1); split16(v.z,h2,l2); split16(v.w,h3,l3);
        *(__half2*)(g_ph + i)     = __halves2half2(h0, h1);
        *(__half2*)(g_ph + i + 2) = __halves2half2(h2, h3);
        *(__half2*)(g_pl + i)     = __halves2half2(l0, l1);
        *(__half2*)(g_pl + i + 2) = __halves2half2(l2, l3);
    } else {
        int i = ((blk - 32) * 256 + threadIdx.x) * 4;
        *(float4*)(out + i) = *(const float4*)(bias + (i & 63));
    }
}

// ---------------------------------------------------------------------------
// Kernel 1: qkv = x @ Wqkv, in-kernel f32->f16 convert, 128x128 tiles.
// grid (12, 64), 256 threads.
// ---------------------------------------------------------------------------
#define QK_XS  0
#define QK_WS  18432
#define QK_SMEM 35840
__global__ void __launch_bounds__(256) qkv_kernel(const float* __restrict__ x,
                                                  const float* __restrict__ Wq) {
    extern __shared__ char smem[];
    const uint32_t sb = smem_u32(smem);
    const uint32_t xh_b = sb + QK_XS, ws_b = sb + QK_WS;
    __half* xs = (__half*)(smem + QK_XS);
    __half* ws = (__half*)(smem + QK_WS);
    const int bc = blockIdx.x, br = blockIdx.y, tid = threadIdx.x;
    const int w = tid >> 5, lane = tid & 31;
    const int g = lane >> 2, q = lane & 3;

    // load + convert x tile (128 rows x 64) to fp16 smem
    for (int idx = tid; idx < 2048; idx += 256) {
        int r = idx >> 4, c4 = (idx & 15) * 4;
        float4 v = *(const float4*)(x + (size_t)(br * 128 + r) * 64 + c4);
        *(__half2*)&xs[r * PAD + c4]     = __floats2half2_rn(v.x, v.y);
        *(__half2*)&xs[r * PAD + c4 + 2] = __floats2half2_rn(v.z, v.w);
    }
    // load + convert W tile (64 k x 128 cols)
    for (int idx = tid; idx < 2048; idx += 256) {
        int k = idx >> 5, c4 = (idx & 31) * 4;
        float4 v = *(const float4*)(Wq + (size_t)k * 1536 + bc * 128 + c4);
        *(__half2*)&ws[k * PAD2 + c4]     = __floats2half2_rn(v.x, v.y);
        *(__half2*)&ws[k * PAD2 + c4 + 2] = __floats2half2_rn(v.z, v.w);
    }
    __syncthreads();

    uint32_t ah[4][4];
    {
        uint32_t ra = xh_b + ((w * 16 + (lane & 15)) * PAD + (lane >> 4) * 8) * 2;
        #pragma unroll
        for (int kc = 0; kc < 4; kc++) ldsm4(ah[kc], ra + kc * 32);
    }
    float acc[16][4];
    #pragma unroll
    for (int i = 0; i < 16; i++)
        #pragma unroll
        for (int j = 0; j < 4; j++) acc[i][j] = 0.f;

    const int lm_g = lane >> 3, lm_r = lane & 7;
    const int lm_row = 8 * (lm_g & 1) + lm_r;
    const int lm_col = 8 * (lm_g >> 1);
    #pragma unroll
    for (int kc = 0; kc < 4; kc++) {
        #pragma unroll
        for (int cp = 0; cp < 8; cp++) {
            uint32_t off = (((kc * 16 + lm_row) * PAD2 + cp * 16 + lm_col)) * 2;
            uint32_t mh[4];
            ldsm4t(mh, ws_b + off);
            mma_f16(acc[2*cp],   ah[kc][0],ah[kc][1],ah[kc][2],ah[kc][3], mh[0],mh[1]);
            mma_f16(acc[2*cp+1], ah[kc][0],ah[kc][1],ah[kc][2],ah[kc][3], mh[2],mh[3]);
        }
    }

    const float sc = (bc < 4) ? (SCALE * LOG2E) : 1.0f;
    __syncthreads();
    __half* os = (__half*)smem;
    #pragma unroll
    for (int nt = 0; nt < 16; nt++) {
        int c = nt * 8 + 2 * q;
        *(__half2*)&os[(w*16 + g)*PAD2 + c]     = __floats2half2_rn(acc[nt][0]*sc, acc[nt][1]*sc);
        *(__half2*)&os[(w*16 + g + 8)*PAD2 + c] = __floats2half2_rn(acc[nt][2]*sc, acc[nt][3]*sc);
    }
    __syncthreads();
    const int qkvi = bc >> 2;
    const int hb = (bc & 3) * 2;
    __half* gq = (qkvi == 0) ? g_Qh : (qkvi == 1) ? g_Kh : g_Vh;
    const int b_ = br >> 4, n0 = (br & 15) * 128;
    for (int idx = tid; idx < 2048; idx += 256) {
        int r = idx >> 4, hh = (idx >> 3) & 1, u = idx & 7;
        __half* dst = gq + (((size_t)(b_*HH + hb + hh)) * NN + n0 + r) * CC + u * 8;
        *(uint4*)dst = *(uint4*)&os[r * PAD2 + hh * 64 + u * 8];
    }
}

// ---------------------------------------------------------------------------
// Kernel 2: flash attention with fused output projection (R12 structure).
// grid (16, 8, 4), 256 threads, 3 CTAs/SM.
// ---------------------------------------------------------------------------
#define SMA_Q  0
#define SMA_K0 18432
#define SMA_K1 27648
#define SMA_V0 36864
#define SMA_V1 46080
#define SMA_TOTAL 55296
__global__ void __launch_bounds__(256, 3) attn_kernel(float* __restrict__ out) {
    extern __shared__ char smem[];
    const uint32_t sb = smem_u32(smem);
    const int tid = threadIdx.x, w = tid >> 5, lane = tid & 31;
    const int g = lane >> 2, q = lane & 3;
    const int h = blockIdx.y, b = blockIdx.z;

    const __half* Qg = g_Qh + ((size_t)(b*HH + h))*NN*CC + (size_t)blockIdx.x * 128 * CC;
    const __half* Kg = g_Kh + ((size_t)(b*HH + h))*NN*CC;
    const __half* Vg = g_Vh + ((size_t)(b*HH + h))*NN*CC;

    for (int idx = tid; idx < 1024; idx += 256) {
        int r = idx >> 3, s = idx & 7;
        cp16(sb + SMA_Q + (r * PAD + s * 8) * 2, Qg + r * 64 + s * 8);
    }
    for (int idx = tid; idx < 512; idx += 256) {
        int r = idx >> 3, s = idx & 7;
        cp16(sb + SMA_K0 + (r * PAD + s * 8) * 2, Kg + r * 64 + s * 8);
        cp16(sb + SMA_V0 + (r * PAD + s * 8) * 2, Vg + r * 64 + s * 8);
    }
    CP_COMMIT();
    CP_WAIT(0);
    __syncthreads();

    uint32_t qf[4][4];
    {
        uint32_t qa = sb + SMA_Q + ((w*16 + (lane & 15)) * PAD + (lane >> 4) * 8) * 2;
        #pragma unroll
        for (int kc = 0; kc < 4; kc++) ldsm4(qf[kc], qa + kc * 32);
    }

    float o[8][4];
    #pragma unroll
    for (int i = 0; i < 8; i++)
        #pragma unroll
        for (int j = 0; j < 4; j++) o[i][j] = 0.f;
    float lsum0 = 0.f, lsum1 = 0.f;

    const int lm_g = lane >> 3, lm_r = lane & 7;
    const int lm_row = 8 * (lm_g & 1) + lm_r;
    const int lm_col = 8 * (lm_g >> 1);

    for (int t = 0; t < 32; t++) {
        const uint32_t kb = sb + ((t & 1) ? SMA_K1 : SMA_K0);
        const uint32_t vb = sb + ((t & 1) ? SMA_V1 : SMA_V0);

        if (t < 31) {
            const uint32_t kn = sb + ((t & 1) ? SMA_K0 : SMA_K1);
            const uint32_t vn = sb + ((t & 1) ? SMA_V0 : SMA_V1);
            const __half* Kt = Kg + (size_t)(t + 1) * 64 * 64;
            const __half* Vt = Vg + (size_t)(t + 1) * 64 * 64;
            #pragma unroll
            for (int idx = tid; idx < 512; idx += 256) {
                int r = idx >> 3, s = idx & 7;
                cp16(kn + (r * PAD + s * 8) * 2, Kt + r * 64 + s * 8);
                cp16(vn + (r * PAD + s * 8) * 2, Vt + r * 64 + s * 8);
            }
            CP_COMMIT();
        }

        // ---- QK^T (f16 accumulate) ----
        uint32_t ph[8][2];
        #pragma unroll
        for (int i = 0; i < 8; i++) { ph[i][0] = 0u; ph[i][1] = 0u; }

        const uint32_t krow = kb + ((lane & 15) * PAD + (lane >> 4) * 8) * 2;
        #pragma unroll
        for (int kc = 0; kc < 4; kc++) {
            #pragma unroll
            for (int np = 0; np < 4; np++) {
                uint32_t m[4];
                ldsm4(m, krow + (np * 16 * PAD) * 2 + kc * 32);
                mma_f16h(ph[2*np],   qf[kc][0],qf[kc][1],qf[kc][2],qf[kc][3], m[0], m[2]);
                mma_f16h(ph[2*np+1], qf[kc][0],qf[kc][1],qf[kc][2],qf[kc][3], m[1], m[3]);
            }
        }

        // ---- softmax ----
        #pragma unroll
        for (int nt = 0; nt < 8; nt++) {
            ph[nt][0] = ex2h2(ph[nt][0]);
            ph[nt][1] = ex2h2(ph[nt][1]);
        }
        {
            uint32_t s0 = hadd2u(ph[0][0], ph[1][0]);
            uint32_t s1 = hadd2u(ph[2][0], ph[3][0]);
            uint32_t s2 = hadd2u(ph[4][0], ph[5][0]);
            uint32_t s3 = hadd2u(ph[6][0], ph[7][0]);
            uint32_t ss = hadd2u(hadd2u(s0, s1), hadd2u(s2, s3));
            float2 f = __half22float2(*(__half2*)&ss);
            lsum0 += f.x + f.y;
            s0 = hadd2u(ph[0][1], ph[1][1]);
            s1 = hadd2u(ph[2][1], ph[3][1]);
            s2 = hadd2u(ph[4][1], ph[5][1]);
            s3 = hadd2u(ph[6][1], ph[7][1]);
            ss = hadd2u(hadd2u(s0, s1), hadd2u(s2, s3));
            f = __half22float2(*(__half2*)&ss);
            lsum1 += f.x + f.y;
        }

        // ---- P @ V (f32 accumulate) ----
        #pragma unroll
        for (int kc = 0; kc < 4; kc++) {
            uint32_t a0 = ph[2*kc][0],   a1 = ph[2*kc][1];
            uint32_t a2 = ph[2*kc+1][0], a3 = ph[2*kc+1][1];
            #pragma unroll
            for (int cp = 0; cp < 4; cp++) {
                uint32_t m[4];
                ldsm4t(m, vb + (((kc * 16 + lm_row) * PAD + cp * 16 + lm_col)) * 2);
                mma_f16(o[2*cp],   a0, a1, a2, a3, m[0], m[1]);
                mma_f16(o[2*cp+1], a0, a1, a2, a3, m[2], m[3]);
            }
        }

        if (t < 31) { CP_WAIT(0); }
        __syncthreads();
    }

    // ---- fused projection epilogue ----
    // stage this head's Wp slice (hi/lo) into the freed K smem
    {
        const __half* wph = g_ph + (size_t)h * 64 * 64;
        const __half* wpl = g_pl + (size_t)h * 64 * 64;
        for (int idx = tid; idx < 512; idx += 256) {
            int r = idx >> 3, s = idx & 7;
            cp16(sb + SMA_K0 + (r * PAD + s * 8) * 2, wph + r * 64 + s * 8);
            cp16(sb + SMA_K1 + (r * PAD + s * 8) * 2, wpl + r * 64 + s * 8);
        }
        CP_COMMIT();
    }

    // normalize + pack O rows into A-fragments (overlaps the Wp loads)
    lsum0 += __shfl_xor_sync(0xFFFFFFFFu, lsum0, 1);
    lsum0 += __shfl_xor_sync(0xFFFFFFFFu, lsum0, 2);
    lsum1 += __shfl_xor_sync(0xFFFFFFFFu, lsum1, 1);
    lsum1 += __shfl_xor_sync(0xFFFFFFFFu, lsum1, 2);
    const float inv0 = 1.f / lsum0, inv1 = 1.f / lsum1;
    uint32_t of16[8][2];
    #pragma unroll
    for (int nt = 0; nt < 8; nt++) {
        of16[nt][0] = packh2(o[nt][0]*inv0, o[nt][1]*inv0);
        of16[nt][1] = packh2(o[nt][2]*inv1, o[nt][3]*inv1);
    }

    float acc[8][4];
    #pragma unroll
    for (int i = 0; i < 8; i++)
        #pragma unroll
        for (int j = 0; j < 4; j++) acc[i][j] = 0.f;

    CP_WAIT(0);
    __syncthreads();

    #pragma unroll
    for (int kc = 0; kc < 4; kc++) {
        uint32_t a0 = of16[2*kc][0],   a1 = of16[2*kc][1];
        uint32_t a2 = of16[2*kc+1][0], a3 = of16[2*kc+1][1];
        #pragma unroll
        for (int cp = 0; cp < 4; cp++) {
            uint32_t off = (((kc * 16 + lm_row) * PAD + cp * 16 + lm_col)) * 2;
            uint32_t mh[4], ml[4];
            ldsm4t(mh, sb + SMA_K0 + off);
            ldsm4t(ml, sb + SMA_K1 + off);
            mma_f16(acc[2*cp],   a0, a1, a2, a3, mh[0], mh[1]);
            mma_f16(acc[2*cp+1], a0, a1, a2, a3, mh[2], mh[3]);
            mma_f16(acc[2*cp],   a0, a1, a2, a3, ml[0], ml[1]);
            mma_f16(acc[2*cp+1], a0, a1, a2, a3, ml[2], ml[3]);
        }
    }

    // vector reduce into out (bias pre-filled by prepass)
    const int row0 = b * NN + blockIdx.x * 128 + w * 16 + g;
    float* o0 = out + (size_t)row0 * 64;
    float* o1 = out + (size_t)(row0 + 8) * 64;
    #pragma unroll
    for (int nt = 0; nt < 8; nt++) {
        int c = nt * 8 + 2 * q;
        redg2(o0 + c, acc[nt][0], acc[nt][1]);
        redg2(o1 + c, acc[nt][2], acc[nt][3]);
    }
}

// ---------------------------------------------------------------------------
extern "C" void kernel_launch(void* const* d_in, const int* in_sizes, int n_in,
                              void* d_out, int out_size) {
    const float* x    = (const float*)d_in[0];
    const float* Wqkv = (const float*)d_in[1];
    const float* Wp   = (const float*)d_in[2];
    const float* bp   = (const float*)d_in[3];
    float* out = (float*)d_out;

    cudaFuncSetAttribute(qkv_kernel,  cudaFuncAttributeMaxDynamicSharedMemorySize, QK_SMEM);
    cudaFuncSetAttribute(attn_kernel, cudaFuncAttributeMaxDynamicSharedMemorySize, SMA_TOTAL);

    prepass<<<544, 256>>>(Wp, bp, out);
    qkv_kernel<<<dim3(12, 64), 256, QK_SMEM>>>(x, Wqkv);
    attn_kernel<<<dim3(16, 8, 4), 256, SMA_TOTAL>>>(out);
}

// round 16
// speedup vs baseline: 1.0461x; 1.0461x over previous
#include <cuda_runtime.h>
#include <cuda_fp16.h>
#include <cstdint>
#include <math.h>

#define BB 4
#define NN 2048
#define CC 64
#define HH 8
#define SCALE 0.125f
#define LOG2E 1.44269504088896340736f

// Scratch (allocation-free)
__device__ __half g_xh[BB*NN*CC];                          // x rounded fp16
__device__ __half g_wh[CC*3*HH*CC];                        // Wqkv rounded fp16
__device__ __half g_ph[HH*CC*CC],  g_pl[HH*CC*CC];         // Wproj split hi/lo
__device__ __half g_Qh[BB*HH*NN*CC];
__device__ __half g_Kh[BB*HH*NN*CC];
__device__ __half g_Vh[BB*HH*NN*CC];

__device__ __forceinline__ uint32_t smem_u32(const void* p) {
    uint32_t a;
    asm("{ .reg .u64 t; cvta.to.shared.u64 t, %1; cvt.u32.u64 %0, t; }" : "=r"(a) : "l"(p));
    return a;
}
__device__ __forceinline__ void cp16(uint32_t dst, const void* src) {
    asm volatile("cp.async.cg.shared.global [%0], [%1], 16;" :: "r"(dst), "l"(src));
}
#define CP_COMMIT() asm volatile("cp.async.commit_group;" ::: "memory")
#define CP_WAIT(n)  asm volatile("cp.async.wait_group %0;" :: "n"(n) : "memory")

__device__ __forceinline__ void mma_f16(float* c, uint32_t a0, uint32_t a1,
                                        uint32_t a2, uint32_t a3,
                                        uint32_t b0, uint32_t b1) {
    asm volatile(
        "mma.sync.aligned.m16n8k16.row.col.f32.f16.f16.f32 "
        "{%0,%1,%2,%3}, {%4,%5,%6,%7}, {%8,%9}, {%0,%1,%2,%3};"
        : "+f"(c[0]), "+f"(c[1]), "+f"(c[2]), "+f"(c[3])
        : "r"(a0), "r"(a1), "r"(a2), "r"(a3), "r"(b0), "r"(b1));
}
__device__ __forceinline__ void mma_f16h(uint32_t* c, uint32_t a0, uint32_t a1,
                                         uint32_t a2, uint32_t a3,
                                         uint32_t b0, uint32_t b1) {
    asm volatile(
        "mma.sync.aligned.m16n8k16.row.col.f16.f16.f16.f16 "
        "{%0,%1}, {%2,%3,%4,%5}, {%6,%7}, {%0,%1};"
        : "+r"(c[0]), "+r"(c[1])
        : "r"(a0), "r"(a1), "r"(a2), "r"(a3), "r"(b0), "r"(b1));
}
__device__ __forceinline__ void ldsm4(uint32_t* r, uint32_t addr) {
    asm volatile("ldmatrix.sync.aligned.m8n8.x4.shared.b16 {%0,%1,%2,%3}, [%4];"
                 : "=r"(r[0]), "=r"(r[1]), "=r"(r[2]), "=r"(r[3]) : "r"(addr));
}
__device__ __forceinline__ void ldsm4t(uint32_t* r, uint32_t addr) {
    asm volatile("ldmatrix.sync.aligned.m8n8.x4.trans.shared.b16 {%0,%1,%2,%3}, [%4];"
                 : "=r"(r[0]), "=r"(r[1]), "=r"(r[2]), "=r"(r[3]) : "r"(addr));
}
__device__ __forceinline__ uint32_t ex2h2(uint32_t p) {
    uint32_t r; asm("ex2.approx.f16x2 %0, %1;" : "=r"(r) : "r"(p)); return r;
}
__device__ __forceinline__ uint32_t hadd2u(uint32_t a, uint32_t b) {
    __half2 r = __hadd2(*(__half2*)&a, *(__half2*)&b);
    return *(uint32_t*)&r;
}
__device__ __forceinline__ uint32_t packh2(float a, float b) {
    __half2 h = __floats2half2_rn(a, b);
    return *(uint32_t*)&h;
}
__device__ __forceinline__ void split16(float v, __half& hi, __half& lo) {
    hi = __float2half_rn(v);
    lo = __float2half_rn(v - __half2float(hi));
}

#define PAD  72
#define PAD2 136

// ---------------------------------------------------------------------------
// Merged pre-pass: convert inputs + pre-fill out with bias
// blocks [0,512): x  [512,608): Wqkv  [608,640): Wproj  [640,1152): out=bias
// ---------------------------------------------------------------------------
__global__ void __launch_bounds__(256) prepass(const float* __restrict__ x,
                                               const float* __restrict__ Wq,
                                               const float* __restrict__ Wp,
                                               const float* __restrict__ bias,
                                               float* __restrict__ out) {
    const int blk = blockIdx.x;
    if (blk < 512) {
        int i = (blk * 256 + threadIdx.x) * 4;
        float4 v = *(const float4*)(x + i);
        *(__half2*)(g_xh + i)     = __floats2half2_rn(v.x, v.y);
        *(__half2*)(g_xh + i + 2) = __floats2half2_rn(v.z, v.w);
    } else if (blk < 608) {
        int i = ((blk - 512) * 256 + threadIdx.x) * 4;
        float4 v = *(const float4*)(Wq + i);
        *(__half2*)(g_wh + i)     = __floats2half2_rn(v.x, v.y);
        *(__half2*)(g_wh + i + 2) = __floats2half2_rn(v.z, v.w);
    } else if (blk < 640) {
        int i = ((blk - 608) * 256 + threadIdx.x) * 4;
        float4 v = *(const float4*)(Wp + i);
        __half h0,l0,h1,l1,h2,l2,h3,l3;
        split16(v.x,h0,l0); split16(v.y,h1,l1); split16(v.z,h2,l2); split16(v.w,h3,l3);
        *(__half2*)(g_ph + i)     = __halves2half2(h0, h1);
        *(__half2*)(g_ph + i + 2) = __halves2half2(h2, h3);
        *(__half2*)(g_pl + i)     = __halves2half2(l0, l1);
        *(__half2*)(g_pl + i + 2) = __halves2half2(l2, l3);
    } else {
        int i = ((blk - 640) * 256 + threadIdx.x) * 4;
        int c = i & 63;
        *(float4*)(out + i) = *(const float4*)(bias + c);
    }
}

// ---------------------------------------------------------------------------
// Kernel 1: qkv = x @ Wqkv, pure fp16 mma, 128x128 tiles. grid (12, 64)
// ---------------------------------------------------------------------------
#define QK_XS  0
#define QK_WS  18432
#define QK_SMEM 35840
__global__ void __launch_bounds__(256) qkv_kernel() {
    extern __shared__ char smem[];
    const uint32_t sb = smem_u32(smem);
    const uint32_t xh_b = sb + QK_XS, ws_b = sb + QK_WS;
    const int bc = blockIdx.x, br = blockIdx.y, tid = threadIdx.x;
    const int w = tid >> 5, lane = tid & 31;
    const int g = lane >> 2, q = lane & 3;

    for (int idx = tid; idx < 1024; idx += 256) {
        int r = idx >> 3, s = idx & 7;
        cp16(xh_b + (r * PAD + s * 8) * 2, g_xh + (size_t)(br * 128 + r) * 64 + s * 8);
    }
    for (int idx = tid; idx < 1024; idx += 256) {
        int k = idx >> 4, s = idx & 15;
        cp16(ws_b + (k * PAD2 + s * 8) * 2, g_wh + (size_t)k * 1536 + bc * 128 + s * 8);
    }
    CP_COMMIT();
    CP_WAIT(0);
    __syncthreads();

    uint32_t ah[4][4];
    {
        uint32_t ra = xh_b + ((w * 16 + (lane & 15)) * PAD + (lane >> 4) * 8) * 2;
        #pragma unroll
        for (int kc = 0; kc < 4; kc++) ldsm4(ah[kc], ra + kc * 32);
    }
    float acc[16][4];
    #pragma unroll
    for (int i = 0; i < 16; i++)
        #pragma unroll
        for (int j = 0; j < 4; j++) acc[i][j] = 0.f;

    const int lm_g = lane >> 3, lm_r = lane & 7;
    const int lm_row = 8 * (lm_g & 1) + lm_r;
    const int lm_col = 8 * (lm_g >> 1);
    #pragma unroll
    for (int kc = 0; kc < 4; kc++) {
        #pragma unroll
        for (int cp = 0; cp < 8; cp++) {
            uint32_t off = (((kc * 16 + lm_row) * PAD2 + cp * 16 + lm_col)) * 2;
            uint32_t mh[4];
            ldsm4t(mh, ws_b + off);
            mma_f16(acc[2*cp],   ah[kc][0],ah[kc][1],ah[kc][2],ah[kc][3], mh[0],mh[1]);
            mma_f16(acc[2*cp+1], ah[kc][0],ah[kc][1],ah[kc][2],ah[kc][3], mh[2],mh[3]);
        }
    }

    const float sc = (bc < 4) ? (SCALE * LOG2E) : 1.0f;
    __syncthreads();
    __half* os = (__half*)smem;
    #pragma unroll
    for (int nt = 0; nt < 16; nt++) {
        int c = nt * 8 + 2 * q;
        *(__half2*)&os[(w*16 + g)*PAD2 + c]     = __floats2half2_rn(acc[nt][0]*sc, acc[nt][1]*sc);
        *(__half2*)&os[(w*16 + g + 8)*PAD2 + c] = __floats2half2_rn(acc[nt][2]*sc, acc[nt][3]*sc);
    }
    __syncthreads();
    const int qkvi = bc >> 2;
    const int hb = (bc & 3) * 2;
    __half* gq = (qkvi == 0) ? g_Qh : (qkvi == 1) ? g_Kh : g_Vh;
    const int b_ = br >> 4, n0 = (br & 15) * 128;
    for (int idx = tid; idx < 2048; idx += 256) {
        int r = idx >> 4, hh = (idx >> 3) & 1, u = idx & 7;
        __half* dst = gq + (((size_t)(b_*HH + hb + hh)) * NN + n0 + r) * CC + u * 8;
        *(uint4*)dst = *(uint4*)&os[r * PAD2 + hh * 64 + u * 8];
    }
}

// ---------------------------------------------------------------------------
// Kernel 2: flash attention WITH FUSED OUTPUT PROJECTION.
// q-tile 128, f16-accum QK + f32-accum PV; epilogue applies this head's
// 64-deep slice of Wproj (split hi/lo) and atomicAdds into out (pre-filled
// with bias). grid (16, 8, 4), 256 threads, 3 CTAs/SM.
// ---------------------------------------------------------------------------
#define SMA_Q  0
#define SMA_K0 18432
#define SMA_K1 27648
#define SMA_V0 36864
#define SMA_V1 46080
#define SMA_TOTAL 55296
__global__ void __launch_bounds__(256, 3) attn_kernel(float* __restrict__ out) {
    extern __shared__ char smem[];
    const uint32_t sb = smem_u32(smem);
    const int tid = threadIdx.x, w = tid >> 5, lane = tid & 31;
    const int g = lane >> 2, q = lane & 3;
    const int h = blockIdx.y, b = blockIdx.z;

    const __half* Qg = g_Qh + ((size_t)(b*HH + h))*NN*CC + (size_t)blockIdx.x * 128 * CC;
    const __half* Kg = g_Kh + ((size_t)(b*HH + h))*NN*CC;
    const __half* Vg = g_Vh + ((size_t)(b*HH + h))*NN*CC;

    for (int idx = tid; idx < 1024; idx += 256) {
        int r = idx >> 3, s = idx & 7;
        cp16(sb + SMA_Q + (r * PAD + s * 8) * 2, Qg + r * 64 + s * 8);
    }
    for (int idx = tid; idx < 512; idx += 256) {
        int r = idx >> 3, s = idx & 7;
        cp16(sb + SMA_K0 + (r * PAD + s * 8) * 2, Kg + r * 64 + s * 8);
        cp16(sb + SMA_V0 + (r * PAD + s * 8) * 2, Vg + r * 64 + s * 8);
    }
    CP_COMMIT();
    CP_WAIT(0);
    __syncthreads();

    uint32_t qf[4][4];
    {
        uint32_t qa = sb + SMA_Q + ((w*16 + (lane & 15)) * PAD + (lane >> 4) * 8) * 2;
        #pragma unroll
        for (int kc = 0; kc < 4; kc++) ldsm4(qf[kc], qa + kc * 32);
    }

    float o[8][4];
    #pragma unroll
    for (int i = 0; i < 8; i++)
        #pragma unroll
        for (int j = 0; j < 4; j++) o[i][j] = 0.f;
    float lsum0 = 0.f, lsum1 = 0.f;

    const int lm_g = lane >> 3, lm_r = lane & 7;
    const int lm_row = 8 * (lm_g & 1) + lm_r;
    const int lm_col = 8 * (lm_g >> 1);

    for (int t = 0; t < 32; t++) {
        const uint32_t kb = sb + ((t & 1) ? SMA_K1 : SMA_K0);
        const uint32_t vb = sb + ((t & 1) ? SMA_V1 : SMA_V0);

        if (t < 31) {
            const uint32_t kn = sb + ((t & 1) ? SMA_K0 : SMA_K1);
            const uint32_t vn = sb + ((t & 1) ? SMA_V0 : SMA_V1);
            const __half* Kt = Kg + (size_t)(t + 1) * 64 * 64;
            const __half* Vt = Vg + (size_t)(t + 1) * 64 * 64;
            #pragma unroll
            for (int idx = tid; idx < 512; idx += 256) {
                int r = idx >> 3, s = idx & 7;
                cp16(kn + (r * PAD + s * 8) * 2, Kt + r * 64 + s * 8);
                cp16(vn + (r * PAD + s * 8) * 2, Vt + r * 64 + s * 8);
            }
            CP_COMMIT();
        }

        // ---- QK^T (f16 accumulate) ----
        uint32_t ph[8][2];
        #pragma unroll
        for (int i = 0; i < 8; i++) { ph[i][0] = 0u; ph[i][1] = 0u; }

        const uint32_t krow = kb + ((lane & 15) * PAD + (lane >> 4) * 8) * 2;
        #pragma unroll
        for (int kc = 0; kc < 4; kc++) {
            #pragma unroll
            for (int np = 0; np < 4; np++) {
                uint32_t m[4];
                ldsm4(m, krow + (np * 16 * PAD) * 2 + kc * 32);
                mma_f16h(ph[2*np],   qf[kc][0],qf[kc][1],qf[kc][2],qf[kc][3], m[0], m[2]);
                mma_f16h(ph[2*np+1], qf[kc][0],qf[kc][1],qf[kc][2],qf[kc][3], m[1], m[3]);
            }
        }

        // ---- softmax ----
        #pragma unroll
        for (int nt = 0; nt < 8; nt++) {
            ph[nt][0] = ex2h2(ph[nt][0]);
            ph[nt][1] = ex2h2(ph[nt][1]);
        }
        {
            uint32_t s0 = hadd2u(ph[0][0], ph[1][0]);
            uint32_t s1 = hadd2u(ph[2][0], ph[3][0]);
            uint32_t s2 = hadd2u(ph[4][0], ph[5][0]);
            uint32_t s3 = hadd2u(ph[6][0], ph[7][0]);
            uint32_t ss = hadd2u(hadd2u(s0, s1), hadd2u(s2, s3));
            float2 f = __half22float2(*(__half2*)&ss);
            lsum0 += f.x + f.y;
            s0 = hadd2u(ph[0][1], ph[1][1]);
            s1 = hadd2u(ph[2][1], ph[3][1]);
            s2 = hadd2u(ph[4][1], ph[5][1]);
            s3 = hadd2u(ph[6][1], ph[7][1]);
            ss = hadd2u(hadd2u(s0, s1), hadd2u(s2, s3));
            f = __half22float2(*(__half2*)&ss);
            lsum1 += f.x + f.y;
        }

        // ---- P @ V (f32 accumulate) ----
        #pragma unroll
        for (int kc = 0; kc < 4; kc++) {
            uint32_t a0 = ph[2*kc][0],   a1 = ph[2*kc][1];
            uint32_t a2 = ph[2*kc+1][0], a3 = ph[2*kc+1][1];
            #pragma unroll
            for (int cp = 0; cp < 4; cp++) {
                uint32_t m[4];
                ldsm4t(m, vb + (((kc * 16 + lm_row) * PAD + cp * 16 + lm_col)) * 2);
                mma_f16(o[2*cp],   a0, a1, a2, a3, m[0], m[1]);
                mma_f16(o[2*cp+1], a0, a1, a2, a3, m[2], m[3]);
            }
        }

        if (t < 31) { CP_WAIT(0); }
        __syncthreads();
    }

    // ---- fused projection epilogue ----
    // stage this head's Wp slice (hi/lo) into the freed K smem
    {
        const __half* wph = g_ph + (size_t)h * 64 * 64;
        const __half* wpl = g_pl + (size_t)h * 64 * 64;
        for (int idx = tid; idx < 512; idx += 256) {
            int r = idx >> 3, s = idx & 7;
            cp16(sb + SMA_K0 + (r * PAD + s * 8) * 2, wph + r * 64 + s * 8);
            cp16(sb + SMA_K1 + (r * PAD + s * 8) * 2, wpl + r * 64 + s * 8);
        }
        CP_COMMIT();
    }

    // normalize + pack O rows into A-fragments (same layout trick as P)
    lsum0 += __shfl_xor_sync(0xFFFFFFFFu, lsum0, 1);
    lsum0 += __shfl_xor_sync(0xFFFFFFFFu, lsum0, 2);
    lsum1 += __shfl_xor_sync(0xFFFFFFFFu, lsum1, 1);
    lsum1 += __shfl_xor_sync(0xFFFFFFFFu, lsum1, 2);
    const float inv0 = 1.f / lsum0, inv1 = 1.f / lsum1;
    uint32_t of16[8][2];
    #pragma unroll
    for (int nt = 0; nt < 8; nt++) {
        of16[nt][0] = packh2(o[nt][0]*inv0, o[nt][1]*inv0);
        of16[nt][1] = packh2(o[nt][2]*inv1, o[nt][3]*inv1);
    }

    float acc[8][4];
    #pragma unroll
    for (int i = 0; i < 8; i++)
        #pragma unroll
        for (int j = 0; j < 4; j++) acc[i][j] = 0.f;

    CP_WAIT(0);
    __syncthreads();

    #pragma unroll
    for (int kc = 0; kc < 4; kc++) {
        uint32_t a0 = of16[2*kc][0],   a1 = of16[2*kc][1];
        uint32_t a2 = of16[2*kc+1][0], a3 = of16[2*kc+1][1];
        #pragma unroll
        for (int cp = 0; cp < 4; cp++) {
            uint32_t off = (((kc * 16 + lm_row) * PAD + cp * 16 + lm_col)) * 2;
            uint32_t mh[4], ml[4];
            ldsm4t(mh, sb + SMA_K0 + off);
            ldsm4t(ml, sb + SMA_K1 + off);
            mma_f16(acc[2*cp],   a0, a1, a2, a3, mh[0], mh[1]);
            mma_f16(acc[2*cp+1], a0, a1, a2, a3, mh[2], mh[3]);
            mma_f16(acc[2*cp],   a0, a1, a2, a3, ml[0], ml[1]);
            mma_f16(acc[2*cp+1], a0, a1, a2, a3, ml[2], ml[3]);
        }
    }

    // atomic accumulate into out (bias pre-filled by prepass)
    const int row0 = b * NN + blockIdx.x * 128 + w * 16 + g;
    float* o0 = out + (size_t)row0 * 64;
    float* o1 = out + (size_t)(row0 + 8) * 64;
    #pragma unroll
    for (int nt = 0; nt < 8; nt++) {
        int c = nt * 8 + 2 * q;
        atomicAdd(o0 + c,     acc[nt][0]);
        atomicAdd(o0 + c + 1, acc[nt][1]);
        atomicAdd(o1 + c,     acc[nt][2]);
        atomicAdd(o1 + c + 1, acc[nt][3]);
    }
}

// ---------------------------------------------------------------------------
extern "C" void kernel_launch(void* const* d_in, const int* in_sizes, int n_in,
                              void* d_out, int out_size) {
    const float* x    = (const float*)d_in[0];
    const float* Wqkv = (const float*)d_in[1];
    const float* Wp   = (const float*)d_in[2];
    const float* bp   = (const float*)d_in[3];
    float* out = (float*)d_out;

    cudaFuncSetAttribute(qkv_kernel,  cudaFuncAttributeMaxDynamicSharedMemorySize, QK_SMEM);
    cudaFuncSetAttribute(attn_kernel, cudaFuncAttributeMaxDynamicSharedMemorySize, SMA_TOTAL);

    prepass<<<1152, 256>>>(x, Wqkv, Wp, bp, out);
    qkv_kernel<<<dim3(12, 64), 256, QK_SMEM>>>();
    attn_kernel<<<dim3(16, 8, 4), 256, SMA_TOTAL>>>(out);
}